// round 3
// baseline (speedup 1.0000x reference)
#include <cuda_runtime.h>
#include <math.h>

// Shapes (fixed by the problem)
#define HD      1024
#define NROWS   50000
#define GRID_B  304          // 2 CTAs per SM on 152 SMs
#define WARPS_B 8
#define TOT_WARPS (GRID_B * WARPS_B)
#define NP4     (HD / 4)     // 256 float4 positions per 1024-float vector

// Scratch (__device__ globals: no allocation allowed in kernel_launch)
__device__ float  g_q[HD];                       // query vector
__device__ float4 g_epartT[NP4 * GRID_B];        // [position][cta] transposed partials
__device__ float  g_Zpart[GRID_B];               // per-CTA partition-function partials
__device__ float  g_es[HD];                      // unnormalized weighted sum

__device__ __forceinline__ void l2_prefetch_last(const void* p) {
    asm volatile("prefetch.global.L2::evict_last [%0];" :: "l"(p));
}

// ---------------------------------------------------------------------------
// Kernel A: q[j] = dot(W0[j,:], h_t) + b0[j]
//   grid 256 x 256: TWO warps per row (half-row each), combined via shared.
//   Also prefetches W1/W2 (8 MB) into L2 with evict_last so they survive
//   kB's 205 MB H stream and kD hits L2 instead of cold DRAM.
// ---------------------------------------------------------------------------
__global__ __launch_bounds__(256) void kA(const float* __restrict__ W0,
                                          const float* __restrict__ ht,
                                          const float* __restrict__ b0,
                                          const float* __restrict__ W1,
                                          const float* __restrict__ b1,
                                          const float* __restrict__ W2,
                                          const float* __restrict__ b2) {
    __shared__ float4 sht[NP4];
    __shared__ float  sdot[8];
    int tid = threadIdx.x;

    int wid = tid >> 5, lane = tid & 31;
    int rlocal = wid >> 1;                 // 0..3
    int half   = wid & 1;                  // 0 or 1
    int j = blockIdx.x * 4 + rlocal;       // 0..1023
    const float4* wr = (const float4*)(W0 + (size_t)j * HD) + half * 128;

    // Front-batch 4 global vector loads for this half-row.
    float4 w[4];
#pragma unroll
    for (int k = 0; k < 4; k++) w[k] = wr[lane + 32 * k];

    // Prefetch W1/W2 slices into L2 (evict_last). 256 CTAs x 16KB each = 4MB per matrix.
    {
        if (tid < 128) {
            l2_prefetch_last(W1 + (size_t)blockIdx.x * 4096 + (size_t)tid * 32);
        } else {
            l2_prefetch_last(W2 + (size_t)blockIdx.x * 4096 + (size_t)(tid - 128) * 32);
        }
        if (blockIdx.x == 0 && tid < 32) {   // bias vectors (8 KB)
            l2_prefetch_last(b1 + tid * 32);
            l2_prefetch_last(b2 + tid * 32);
        }
    }

    // h_t into shared
    sht[tid] = ((const float4*)ht)[tid];
    __syncthreads();

    const float4* hh = sht + half * 128;
    float s = 0.f;
#pragma unroll
    for (int k = 0; k < 4; k++) {
        float4 h4 = hh[lane + 32 * k];
        s = fmaf(w[k].x, h4.x, s); s = fmaf(w[k].y, h4.y, s);
        s = fmaf(w[k].z, h4.z, s); s = fmaf(w[k].w, h4.w, s);
    }
#pragma unroll
    for (int o = 16; o; o >>= 1) s += __shfl_xor_sync(0xffffffffu, s, o);
    if (lane == 0) sdot[wid] = s;
    __syncthreads();

    if (half == 0 && lane == 0)
        g_q[j] = sdot[wid] + sdot[wid + 1] + b0[j];
}

// ---------------------------------------------------------------------------
// Kernel B: single fused pass over H.
//   Per row i: s = H_i . q ; u = exp(exp(s)) ; Z += u ; e += u * H_i
//   Row stays in registers for both the dot and the accumulate -> H read ONCE.
// ---------------------------------------------------------------------------
__global__ __launch_bounds__(256, 2) void kB(const float* __restrict__ H) {
    __shared__ float4 sq[NP4];                    // query, 4 KB
    __shared__ float4 se[WARPS_B][NP4];           // per-warp partials, 32 KB
    __shared__ float  sZ[WARPS_B];

    int tid = threadIdx.x;
    sq[tid] = ((const float4*)g_q)[tid];
    __syncthreads();

    int wid = tid >> 5, lane = tid & 31;

    float4 e[8];
#pragma unroll
    for (int k = 0; k < 8; k++) e[k] = make_float4(0.f, 0.f, 0.f, 0.f);
    float Z = 0.f;

    int gw = blockIdx.x * WARPS_B + wid;
    for (int row = gw; row < NROWS; row += TOT_WARPS) {
        const float4* hr = (const float4*)(H + (size_t)row * HD);
        float4 r[8];
#pragma unroll
        for (int k = 0; k < 8; k++) r[k] = hr[lane + 32 * k];   // coalesced 512B bursts

        float s = 0.f;
#pragma unroll
        for (int k = 0; k < 8; k++) {
            float4 q4 = sq[lane + 32 * k];
            s = fmaf(r[k].x, q4.x, s); s = fmaf(r[k].y, q4.y, s);
            s = fmaf(r[k].z, q4.z, s); s = fmaf(r[k].w, q4.w, s);
        }
#pragma unroll
        for (int o = 16; o; o >>= 1) s += __shfl_xor_sync(0xffffffffu, s, o);

        // double exp: scores = exp(H@q); softmax numerator exp(scores).
        // softmax(t) == exp(t)/sum(exp(t)) exactly; t bounded by construction.
        float u = expf(expf(s));
        Z += u;
#pragma unroll
        for (int k = 0; k < 8; k++) {
            e[k].x = fmaf(u, r[k].x, e[k].x);
            e[k].y = fmaf(u, r[k].y, e[k].y);
            e[k].z = fmaf(u, r[k].z, e[k].z);
            e[k].w = fmaf(u, r[k].w, e[k].w);
        }
    }

    // CTA-level deterministic reduce of the 8 warp partials
#pragma unroll
    for (int k = 0; k < 8; k++) se[wid][lane + 32 * k] = e[k];
    if (lane == 0) sZ[wid] = Z;
    __syncthreads();

    float4 acc = se[0][tid];
#pragma unroll
    for (int w = 1; w < WARPS_B; w++) {
        float4 v = se[w][tid];
        acc.x += v.x; acc.y += v.y; acc.z += v.z; acc.w += v.w;
    }
    // transposed store: position-major so kernel C reads coalesced
    g_epartT[tid * GRID_B + blockIdx.x] = acc;

    if (tid == 0) {
        float z = 0.f;
#pragma unroll
        for (int w = 0; w < WARPS_B; w++) z += sZ[w];
        g_Zpart[blockIdx.x] = z;
    }
}

// ---------------------------------------------------------------------------
// Kernel C: deterministic reduce of GRID_B partials -> g_es (unnormalized)
//   grid 32 x 256: one warp per float4 position; coalesced contiguous reads.
//   (inputs were just written by kB -> L2-resident)
// ---------------------------------------------------------------------------
__global__ __launch_bounds__(256) void kC() {
    int wid = threadIdx.x >> 5, lane = threadIdx.x & 31;
    int p = blockIdx.x * 8 + wid;                 // 0..255

    float4 acc = make_float4(0.f, 0.f, 0.f, 0.f);
    for (int b = lane; b < GRID_B; b += 32) {
        float4 v = g_epartT[p * GRID_B + b];
        acc.x += v.x; acc.y += v.y; acc.z += v.z; acc.w += v.w;
    }
#pragma unroll
    for (int o = 16; o; o >>= 1) {
        acc.x += __shfl_xor_sync(0xffffffffu, acc.x, o);
        acc.y += __shfl_xor_sync(0xffffffffu, acc.y, o);
        acc.z += __shfl_xor_sync(0xffffffffu, acc.z, o);
        acc.w += __shfl_xor_sync(0xffffffffu, acc.w, o);
    }
    if (lane == 0) ((float4*)g_es)[p] = acc;
}

// ---------------------------------------------------------------------------
// Kernel D: out[j] = tanh( dot(W1[j],e_s)/Z + b1[j] + dot(W2[j],h_t) + b2[j] )
//   W1/W2 should now be L2 hits (evict_last prefetch from kA).
// ---------------------------------------------------------------------------
__global__ __launch_bounds__(256) void kD(const float* __restrict__ W1,
                                          const float* __restrict__ b1,
                                          const float* __restrict__ W2,
                                          const float* __restrict__ b2,
                                          const float* __restrict__ ht,
                                          float* __restrict__ out) {
    __shared__ float4 ses[NP4];
    __shared__ float4 sht[NP4];
    __shared__ float  sZtot;

    int tid = threadIdx.x;
    int wid = tid >> 5, lane = tid & 31;
    int j = blockIdx.x * 8 + wid;                 // 0..1023
    const float4* w1r = (const float4*)(W1 + (size_t)j * HD);
    const float4* w2r = (const float4*)(W2 + (size_t)j * HD);

    // Front-batch all 16 global vector loads BEFORE any dependent work.
    float4 a[8], c[8];
#pragma unroll
    for (int k = 0; k < 8; k++) a[k] = w1r[lane + 32 * k];
#pragma unroll
    for (int k = 0; k < 8; k++) c[k] = w2r[lane + 32 * k];

    ses[tid] = ((const float4*)g_es)[tid];
    sht[tid] = ((const float4*)ht)[tid];
    if (tid < 32) {
        float z = 0.f;
        for (int b = tid; b < GRID_B; b += 32) z += g_Zpart[b];
#pragma unroll
        for (int o = 16; o; o >>= 1) z += __shfl_xor_sync(0xffffffffu, z, o);
        if (tid == 0) sZtot = z;
    }
    __syncthreads();

    float d1 = 0.f, d2 = 0.f;
#pragma unroll
    for (int k = 0; k < 8; k++) {
        float4 v = ses[lane + 32 * k];
        d1 = fmaf(a[k].x, v.x, d1); d1 = fmaf(a[k].y, v.y, d1);
        d1 = fmaf(a[k].z, v.z, d1); d1 = fmaf(a[k].w, v.w, d1);
        float4 h = sht[lane + 32 * k];
        d2 = fmaf(c[k].x, h.x, d2); d2 = fmaf(c[k].y, h.y, d2);
        d2 = fmaf(c[k].z, h.z, d2); d2 = fmaf(c[k].w, h.w, d2);
    }
#pragma unroll
    for (int o = 16; o; o >>= 1) {
        d1 += __shfl_xor_sync(0xffffffffu, d1, o);
        d2 += __shfl_xor_sync(0xffffffffu, d2, o);
    }
    if (lane == 0)
        out[j] = tanhf(d1 / sZtot + b1[j] + d2 + b2[j]);
}

// ---------------------------------------------------------------------------
extern "C" void kernel_launch(void* const* d_in, const int* in_sizes, int n_in,
                              void* d_out, int out_size) {
    const float* H  = (const float*)d_in[0];
    const float* ht = (const float*)d_in[1];
    const float* W0 = (const float*)d_in[2];
    const float* b0 = (const float*)d_in[3];
    const float* W1 = (const float*)d_in[4];
    const float* b1 = (const float*)d_in[5];
    const float* W2 = (const float*)d_in[6];
    const float* b2 = (const float*)d_in[7];
    float* out = (float*)d_out;

    kA<<<256, 256>>>(W0, ht, b0, W1, b1, W2, b2);
    kB<<<GRID_B, 256>>>(H);
    kC<<<32, 256>>>();
    kD<<<128, 256>>>(W1, b1, W2, b2, ht, out);
}

// round 4
// speedup vs baseline: 1.1286x; 1.1286x over previous
#include <cuda_runtime.h>
#include <math.h>

#define HD      1024
#define NROWS   50000
#define GRID    288                  // 2 CTAs/SM on >=144 SMs: co-residency safe
#define WARPS_B 8
#define TOT_WARPS (GRID * WARPS_B)   // 2304
#define NP4     (HD / 4)             // 256 float4 per vector

// Scratch (__device__ globals; zero-initialized once at module load)
__device__ float  g_q[HD];
__device__ float  g_d2[HD];                     // W2@h_t + b2
__device__ float4 g_epartT[NP4 * GRID];         // [position][cta]
__device__ float  g_Zpart[GRID];
__device__ float  g_es[HD];
__device__ float  g_Zsum;
__device__ unsigned g_ctr[4];                   // barrier counters (monotonic)

// Grid-wide barrier, graph-replay safe: counter never resets; the target is
// derived from the observed pre-increment value (old - old%GRID + GRID).
__device__ __forceinline__ void gbar(int k) {
    __syncthreads();
    if (threadIdx.x == 0) {
        __threadfence();                                   // release prior stores
        unsigned old = atomicAdd(&g_ctr[k], 1u);
        unsigned target = old - (old % GRID) + GRID;
        while (*(volatile unsigned*)&g_ctr[k] < target) __nanosleep(32);
    }
    __syncthreads();
    __threadfence();                                       // acquire
}

__global__ __launch_bounds__(256, 2) void fused(
    const float* __restrict__ H,  const float* __restrict__ ht,
    const float* __restrict__ W0, const float* __restrict__ b0,
    const float* __restrict__ W1, const float* __restrict__ b1,
    const float* __restrict__ W2, const float* __restrict__ b2,
    float* __restrict__ out)
{
    __shared__ float4 sv[NP4];                 // ht -> q -> e_s (reused per phase)
    __shared__ float4 se[WARPS_B][NP4];        // phase-2 warp partials / phase-3 reduce buf
    __shared__ float  sZ[WARPS_B];
    __shared__ float  sZr[256];
    __shared__ float  sZtot;

    const int tid  = threadIdx.x;
    const int wid  = tid >> 5, lane = tid & 31;
    const int cta  = blockIdx.x;

    // ---------------- Phase 1: q = W0@ht + b0 ; d2 = W2@ht + b2 --------------
    sv[tid] = ((const float4*)ht)[tid];
    __syncthreads();

    {
        int gw = cta * WARPS_B + wid;          // 0..2303 ; 2048 rows of work
        if (gw < 2048) {
            int j = gw & 1023;
            const float* W = (gw < 1024) ? W0 : W2;
            const float* b = (gw < 1024) ? b0 : b2;
            const float4* wr = (const float4*)(W + (size_t)j * HD);
            float4 w[8];
#pragma unroll
            for (int k = 0; k < 8; k++) w[k] = wr[lane + 32 * k];  // MLP=8
            float s = 0.f;
#pragma unroll
            for (int k = 0; k < 8; k++) {
                float4 h4 = sv[lane + 32 * k];
                s = fmaf(w[k].x, h4.x, s); s = fmaf(w[k].y, h4.y, s);
                s = fmaf(w[k].z, h4.z, s); s = fmaf(w[k].w, h4.w, s);
            }
#pragma unroll
            for (int o = 16; o; o >>= 1) s += __shfl_xor_sync(0xffffffffu, s, o);
            if (lane == 0) { if (gw < 1024) g_q[j] = s + b[j]; else g_d2[j] = s + b[j]; }
        }
    }
    gbar(0);

    // ---------------- Phase 2: single pass over H ----------------------------
    sv[tid] = __ldcg(((const float4*)g_q) + tid);
    __syncthreads();

    float4 e[8];
#pragma unroll
    for (int k = 0; k < 8; k++) e[k] = make_float4(0.f, 0.f, 0.f, 0.f);
    float Z = 0.f;

    for (int row = cta * WARPS_B + wid; row < NROWS; row += TOT_WARPS) {
        const float4* hr = (const float4*)(H + (size_t)row * HD);
        float4 r[8];
#pragma unroll
        for (int k = 0; k < 8; k++) r[k] = hr[lane + 32 * k];

        float s = 0.f;
#pragma unroll
        for (int k = 0; k < 8; k++) {
            float4 q4 = sv[lane + 32 * k];
            s = fmaf(r[k].x, q4.x, s); s = fmaf(r[k].y, q4.y, s);
            s = fmaf(r[k].z, q4.z, s); s = fmaf(r[k].w, q4.w, s);
        }
#pragma unroll
        for (int o = 16; o; o >>= 1) s += __shfl_xor_sync(0xffffffffu, s, o);

        // double exp; softmax(t)=exp(t)/sum(exp(t)) exactly, t bounded.
        float u = expf(expf(s));
        Z += u;
#pragma unroll
        for (int k = 0; k < 8; k++) {
            e[k].x = fmaf(u, r[k].x, e[k].x);
            e[k].y = fmaf(u, r[k].y, e[k].y);
            e[k].z = fmaf(u, r[k].z, e[k].z);
            e[k].w = fmaf(u, r[k].w, e[k].w);
        }
    }

#pragma unroll
    for (int k = 0; k < 8; k++) se[wid][lane + 32 * k] = e[k];
    if (lane == 0) sZ[wid] = Z;
    __syncthreads();

    {
        float4 acc = se[0][tid];
#pragma unroll
        for (int w = 1; w < WARPS_B; w++) {
            float4 v = se[w][tid];
            acc.x += v.x; acc.y += v.y; acc.z += v.z; acc.w += v.w;
        }
        g_epartT[tid * GRID + cta] = acc;      // position-major for phase 3
        if (tid == 0) {
            float z = 0.f;
#pragma unroll
            for (int w = 0; w < WARPS_B; w++) z += sZ[w];
            g_Zpart[cta] = z;
        }
    }
    gbar(1);

    // ---------------- Phase 3: deterministic reduce over 288 partials --------
    if (cta < 256) {                           // one CTA per float4 position
        float4* red = &se[0][0];               // 256-entry reduce buffer
        const float4* src = g_epartT + (size_t)cta * GRID;
        float4 a = __ldcg(src + tid);
        if (tid < GRID - 256) {
            float4 b = __ldcg(src + 256 + tid);
            a.x += b.x; a.y += b.y; a.z += b.z; a.w += b.w;
        }
        red[tid] = a;
        __syncthreads();
#pragma unroll
        for (int o = 128; o; o >>= 1) {
            if (tid < o) {
                float4 b = red[tid + o];
                float4 t = red[tid];
                t.x += b.x; t.y += b.y; t.z += b.z; t.w += b.w;
                red[tid] = t;
            }
            __syncthreads();
        }
        if (tid == 0) ((float4*)g_es)[cta] = red[0];
    } else if (cta == 256) {                   // partition function
        float z = __ldcg(g_Zpart + tid % GRID) * (tid < GRID ? 1.f : 0.f);
        // (tid in [0,256); add the tail entries 256..287 on first 32 threads)
        if (tid < GRID - 256) z += __ldcg(g_Zpart + 256 + tid);
        sZr[tid] = z;
        __syncthreads();
#pragma unroll
        for (int o = 128; o; o >>= 1) {
            if (tid < o) sZr[tid] += sZr[tid + o];
            __syncthreads();
        }
        if (tid == 0) g_Zsum = sZr[0];
    }
    gbar(2);

    // ---------------- Phase 4: out = tanh(W1@e_s/Z + b1 + d2) ----------------
    if (cta < 128) {
        int j = cta * WARPS_B + wid;           // 0..1023
        const float4* w1r = (const float4*)(W1 + (size_t)j * HD);
        float4 a[8];
#pragma unroll
        for (int k = 0; k < 8; k++) a[k] = w1r[lane + 32 * k];  // MLP=8

        sv[tid] = __ldcg(((const float4*)g_es) + tid);
        if (tid == 0) sZtot = __ldcg(&g_Zsum);
        __syncthreads();

        float d1 = 0.f;
#pragma unroll
        for (int k = 0; k < 8; k++) {
            float4 v = sv[lane + 32 * k];
            d1 = fmaf(a[k].x, v.x, d1); d1 = fmaf(a[k].y, v.y, d1);
            d1 = fmaf(a[k].z, v.z, d1); d1 = fmaf(a[k].w, v.w, d1);
        }
#pragma unroll
        for (int o = 16; o; o >>= 1) d1 += __shfl_xor_sync(0xffffffffu, d1, o);
        if (lane == 0)
            out[j] = tanhf(d1 / sZtot + b1[j] + __ldcg(g_d2 + j));
    }
}

// ---------------------------------------------------------------------------
extern "C" void kernel_launch(void* const* d_in, const int* in_sizes, int n_in,
                              void* d_out, int out_size) {
    const float* H  = (const float*)d_in[0];
    const float* ht = (const float*)d_in[1];
    const float* W0 = (const float*)d_in[2];
    const float* b0 = (const float*)d_in[3];
    const float* W1 = (const float*)d_in[4];
    const float* b1 = (const float*)d_in[5];
    const float* W2 = (const float*)d_in[6];
    const float* b2 = (const float*)d_in[7];
    float* out = (float*)d_out;

    fused<<<GRID, 256>>>(H, ht, W0, b0, W1, b1, W2, b2, out);
}